// round 2
// baseline (speedup 1.0000x reference)
#include <cuda_runtime.h>

#define HID     30
#define SEQLEN  784
#define NCLS    10

typedef unsigned long long u64;

// ---- packed f32x2 helpers (Blackwell FFMA2 path) ----
__device__ __forceinline__ u64 dup2(float v) {
    u64 r; asm("mov.b64 %0, {%1,%1};" : "=l"(r) : "f"(v)); return r;
}
__device__ __forceinline__ u64 pk2(float lo, float hi) {
    u64 r; asm("mov.b64 %0, {%1,%2};" : "=l"(r) : "f"(lo), "f"(hi)); return r;
}
__device__ __forceinline__ float2 up2(u64 v) {
    float2 f; asm("mov.b64 {%0,%1}, %2;" : "=f"(f.x), "=f"(f.y) : "l"(v)); return f;
}
__device__ __forceinline__ u64 fma2(u64 a, u64 b, u64 c) {
    u64 d; asm("fma.rn.f32x2 %0, %1, %2, %3;" : "=l"(d) : "l"(a), "l"(b), "l"(c)); return d;
}
__device__ __forceinline__ u64 mul2(u64 a, u64 b) {
    u64 d; asm("mul.rn.f32x2 %0, %1, %2;" : "=l"(d) : "l"(a), "l"(b)); return d;
}

// modReLU: sign(z) * relu(|z| + b). r = max(|z|+b,0) >= 0, so OR in z's sign bit.
__device__ __forceinline__ float mrelu(float z, float b) {
    float t = fabsf(z) + b;        // FADD |.|
    float r = fmaxf(t, 0.0f);      // FMNMX
    unsigned u = __float_as_uint(r) | (__float_as_uint(z) & 0x80000000u);  // LOP3
    return __uint_as_float(u);
}

// 2 threads per batch row (lane, lane^16). Each owns 16 padded j-slots:
// half s owns j = 16s .. 16s+15 (slots >= 30 are zero-padded).
// Shared W layout: sW[m*16 + s*8 + p] = (W'[16s+2p][m], W'[16s+2p+1][m]),
// m = source index (the k in z_j = sum_k h_k W[j][k]), 32 rows (2 pad rows of 0).
__global__ __launch_bounds__(128, 1)
void rnn_modrelu_split2(const float* __restrict__ inputs,
                        const float* __restrict__ W_ih,
                        const float* __restrict__ W_hh,
                        const float* __restrict__ b_mod,
                        const float* __restrict__ W_lin,
                        const float* __restrict__ b_lin,
                        float* __restrict__ out, int B)
{
    __shared__ __align__(16) u64 sW[32 * 16];      // 4 KB
    __shared__ float sWlin[NCLS * HID];
    __shared__ float sblin[NCLS];
    __shared__ float sWih[32];
    __shared__ float sBm[32];

    const int tid = threadIdx.x;
    for (int i = tid; i < 32 * 16; i += 128) {
        int m = i >> 4, c = i & 15;
        int ss = c >> 3, p = c & 7;
        int j0 = 16 * ss + 2 * p, j1 = j0 + 1;
        float a = (m < HID && j0 < HID) ? W_hh[j0 * HID + m] : 0.0f;
        float b = (m < HID && j1 < HID) ? W_hh[j1 * HID + m] : 0.0f;
        sW[i] = pk2(a, b);
    }
    for (int i = tid; i < 32; i += 128) {
        sWih[i] = (i < HID) ? W_ih[i] : 0.0f;
        sBm[i]  = (i < HID) ? b_mod[i] : 0.0f;
    }
    for (int i = tid; i < NCLS * HID; i += 128) sWlin[i] = W_lin[i];
    for (int i = tid; i < NCLS; i += 128) sblin[i] = b_lin[i];
    __syncthreads();

    const int lane = tid & 31;
    const int warp = tid >> 5;
    const int s    = lane >> 4;        // hidden-half id
    const int li   = lane & 15;        // row-within-warp
    int row = blockIdx.x * 64 + warp * 16 + li;
    if (row >= B) row = B - 1;         // safe clamp (keeps warp convergent for shfl)

    // loop invariants in registers
    u64 wih2[8];
#pragma unroll
    for (int p = 0; p < 8; p++) wih2[p] = pk2(sWih[16 * s + 2 * p], sWih[16 * s + 2 * p + 1]);
    float bm[16];
#pragma unroll
    for (int i = 0; i < 16; i++) bm[i] = sBm[16 * s + i];

    const u64* wOwn = sW + (16 * s) * 16 + 8 * s;        // own-phase rows m = 16s+i
    const u64* wOth = sW + (16 * (1 - s)) * 16 + 8 * s;  // other-phase rows m = 16(1-s)+i

    float hown[16], hoth[16];
#pragma unroll
    for (int i = 0; i < 16; i++) { hown[i] = 0.0f; hoth[i] = 0.0f; }

    const float* xrow = inputs + (size_t)row * SEQLEN;
    float x = xrow[0];

    for (int t = 0; t < SEQLEN; ++t) {
        float xn = (t + 1 < SEQLEN) ? __ldg(xrow + t + 1) : 0.0f;  // prefetch

        u64 xd = dup2(x);
        u64 z[8];
#pragma unroll
        for (int p = 0; p < 8; p++) z[p] = mul2(xd, wih2[p]);

#pragma unroll
        for (int i = 0; i < 16; i++) {                 // own-half h contributions
            u64 hd = dup2(hown[i]);
            const ulonglong2* w = (const ulonglong2*)(wOwn + i * 16);
#pragma unroll
            for (int q = 0; q < 4; q++) {              // 4x LDS.128, conflict-free
                ulonglong2 ww = w[q];
                z[2 * q]     = fma2(hd, ww.x, z[2 * q]);
                z[2 * q + 1] = fma2(hd, ww.y, z[2 * q + 1]);
            }
        }
#pragma unroll
        for (int i = 0; i < 16; i++) {                 // partner-half h contributions
            u64 hd = dup2(hoth[i]);
            const ulonglong2* w = (const ulonglong2*)(wOth + i * 16);
#pragma unroll
            for (int q = 0; q < 4; q++) {
                ulonglong2 ww = w[q];
                z[2 * q]     = fma2(hd, ww.x, z[2 * q]);
                z[2 * q + 1] = fma2(hd, ww.y, z[2 * q + 1]);
            }
        }

#pragma unroll
        for (int p = 0; p < 8; p++) {
            float2 zz = up2(z[p]);
            hown[2 * p]     = mrelu(zz.x, bm[2 * p]);
            hown[2 * p + 1] = mrelu(zz.y, bm[2 * p + 1]);
        }
#pragma unroll
        for (int i = 0; i < 16; i++)
            hoth[i] = __shfl_xor_sync(0xffffffffu, hown[i], 16);

        x = xn;
    }

    // logits written by half-0 threads (they hold j0..15 own, j16..29 in hoth)
    if (s == 0) {
        float* orow = out + (size_t)row * NCLS;
#pragma unroll
        for (int c = 0; c < NCLS; c++) {
            float acc = sblin[c];
#pragma unroll
            for (int i = 0; i < 16; i++) acc = fmaf(hown[i], sWlin[c * HID + i], acc);
#pragma unroll
            for (int i = 0; i < 14; i++) acc = fmaf(hoth[i], sWlin[c * HID + 16 + i], acc);
            orow[c] = acc;
        }
    }
}

extern "C" void kernel_launch(void* const* d_in, const int* in_sizes, int n_in,
                              void* d_out, int out_size)
{
    const float* inputs = (const float*)d_in[0];
    const float* W_ih   = (const float*)d_in[1];
    const float* W_hh   = (const float*)d_in[2];
    const float* b_mod  = (const float*)d_in[3];
    const float* W_lin  = (const float*)d_in[4];
    const float* b_lin  = (const float*)d_in[5];
    float* out = (float*)d_out;

    const int B = in_sizes[0] / SEQLEN;
    const int rows_per_block = 64;                  // 128 threads = 2 per row
    const int blocks = (B + rows_per_block - 1) / rows_per_block;
    rnn_modrelu_split2<<<blocks, 128>>>(inputs, W_ih, W_hh, b_mod, W_lin, b_lin, out, B);
}

// round 4
// speedup vs baseline: 1.1267x; 1.1267x over previous
#include <cuda_runtime.h>

#define HID     30
#define SEQLEN  784
#define NCLS    10
#define KSPLIT  16      // k < KSPLIT via shared/FFMA2, k >= KSPLIT via const/scalar
#define WSTRIDE 16

typedef unsigned long long u64;

// W_hh padded rows: cP[j*32 + k] = W_hh[j][k], k-contiguous (pad cols 30,31 unused)
__constant__ float cP[HID * 32];

// ---- packed f32x2 helpers ----
__device__ __forceinline__ u64 dup2(float v) {
    u64 r; asm("mov.b64 %0, {%1,%1};" : "=l"(r) : "f"(v)); return r;
}
__device__ __forceinline__ u64 pk2(float lo, float hi) {
    u64 r; asm("mov.b64 %0, {%1,%2};" : "=l"(r) : "f"(lo), "f"(hi)); return r;
}
__device__ __forceinline__ float2 up2(u64 v) {
    float2 f; asm("mov.b64 {%0,%1}, %2;" : "=f"(f.x), "=f"(f.y) : "l"(v)); return f;
}
__device__ __forceinline__ u64 fma2(u64 a, u64 b, u64 c) {
    u64 d; asm("fma.rn.f32x2 %0, %1, %2, %3;" : "=l"(d) : "l"(a), "l"(b), "l"(c)); return d;
}
__device__ __forceinline__ u64 mul2(u64 a, u64 b) {
    u64 d; asm("mul.rn.f32x2 %0, %1, %2;" : "=l"(d) : "l"(a), "l"(b)); return d;
}

// modReLU: sign(z) * relu(|z| + b)
__device__ __forceinline__ float mrelu(float z, float b) {
    float t = fabsf(z) + b;
    float r = fmaxf(t, 0.0f);
    unsigned u = __float_as_uint(r) | (__float_as_uint(z) & 0x80000000u);
    return __uint_as_float(u);
}

__global__ __launch_bounds__(128, 1)
void rnn_modrelu_hybrid(const float* __restrict__ inputs,
                        const float* __restrict__ W_ih,
                        const float* __restrict__ W_hh,
                        const float* __restrict__ b_mod,
                        const float* __restrict__ W_lin,
                        const float* __restrict__ b_lin,
                        float* __restrict__ out, int B)
{
    // j-pair packed weights for the LDS half: sW[k*16 + p] = (W[2p][k], W[2p+1][k])
    __shared__ __align__(16) u64 sW[KSPLIT * WSTRIDE];
    __shared__ float sWlin[NCLS * HID];
    __shared__ float sblin[NCLS];
    __shared__ float sWih[HID];
    __shared__ float sbm[HID];

    const int tid = threadIdx.x;
    for (int i = tid; i < KSPLIT * 15; i += 128) {
        int k = i / 15, p = i % 15;
        sW[k * WSTRIDE + p] = pk2(W_hh[(2 * p) * HID + k], W_hh[(2 * p + 1) * HID + k]);
    }
    for (int i = tid; i < NCLS * HID; i += 128) sWlin[i] = W_lin[i];
    for (int i = tid; i < HID; i += 128) { sWih[i] = W_ih[i]; sbm[i] = b_mod[i]; }
    for (int i = tid; i < NCLS; i += 128) sblin[i] = b_lin[i];
    __syncthreads();

    const int row = blockIdx.x * blockDim.x + tid;
    if (row >= B) return;

    u64 wih2[15];
#pragma unroll
    for (int p = 0; p < 15; p++) wih2[p] = pk2(sWih[2 * p], sWih[2 * p + 1]);
    float bm[HID];
#pragma unroll
    for (int j = 0; j < HID; j++) bm[j] = sbm[j];

    float h[HID];
#pragma unroll
    for (int j = 0; j < HID; j++) h[j] = 0.0f;

    const float* xrow = inputs + (size_t)row * SEQLEN;
    float x = xrow[0];

    for (int t = 0; t < SEQLEN; ++t) {
        float xn = (t + 1 < SEQLEN) ? __ldg(xrow + t + 1) : 0.0f;

        // ---- packed half: z = x*W_ih + sum_{k<16} h_k W[:,k]  (LDS + FFMA2) ----
        u64 xd = dup2(x);
        u64 z[15];
#pragma unroll
        for (int p = 0; p < 15; p++) z[p] = mul2(xd, wih2[p]);

#pragma unroll
        for (int k = 0; k < KSPLIT; k++) {
            u64 hd = dup2(h[k]);
            const u64* wr = &sW[k * WSTRIDE];
            const ulonglong2* wr2 = (const ulonglong2*)wr;
#pragma unroll
            for (int q = 0; q < 7; q++) {
                ulonglong2 w = wr2[q];
                z[2 * q]     = fma2(hd, w.x, z[2 * q]);
                z[2 * q + 1] = fma2(hd, w.y, z[2 * q + 1]);
            }
            z[14] = fma2(hd, wr[14], z[14]);
        }

        // ---- const half: zs[j] = sum_{k=16..29} h_k * W[j][k]  (LDCU + scalar FFMA) ----
        float zs[HID];
#pragma unroll
        for (int j = 0; j < HID; j++) {
            const float4* cr = (const float4*)&cP[j * 32 + KSPLIT];
            float4 a = cr[0];           // k = 16..19
            float4 b4 = cr[1];          // k = 20..23
            float4 c4 = cr[2];          // k = 24..27
            float s = h[16] * a.x;
            s = fmaf(h[17], a.y, s);
            s = fmaf(h[18], a.z, s);
            s = fmaf(h[19], a.w, s);
            s = fmaf(h[20], b4.x, s);
            s = fmaf(h[21], b4.y, s);
            s = fmaf(h[22], b4.z, s);
            s = fmaf(h[23], b4.w, s);
            s = fmaf(h[24], c4.x, s);
            s = fmaf(h[25], c4.y, s);
            s = fmaf(h[26], c4.z, s);
            s = fmaf(h[27], c4.w, s);
            s = fmaf(h[28], cP[j * 32 + 28], s);
            s = fmaf(h[29], cP[j * 32 + 29], s);
            zs[j] = s;
        }

        // ---- merge + modReLU ----
#pragma unroll
        for (int p = 0; p < 15; p++) {
            float2 zz = up2(z[p]);
            float z0 = zz.x + zs[2 * p];
            float z1 = zz.y + zs[2 * p + 1];
            h[2 * p]     = mrelu(z0, bm[2 * p]);
            h[2 * p + 1] = mrelu(z1, bm[2 * p + 1]);
        }
        x = xn;
    }

    float* orow = out + (size_t)row * NCLS;
#pragma unroll
    for (int c = 0; c < NCLS; c++) {
        float acc = sblin[c];
#pragma unroll
        for (int j = 0; j < HID; j++) acc = fmaf(h[j], sWlin[c * HID + j], acc);
        orow[c] = acc;
    }
}

extern "C" void kernel_launch(void* const* d_in, const int* in_sizes, int n_in,
                              void* d_out, int out_size)
{
    const float* inputs = (const float*)d_in[0];
    const float* W_ih   = (const float*)d_in[1];
    const float* W_hh   = (const float*)d_in[2];
    const float* b_mod  = (const float*)d_in[3];
    const float* W_lin  = (const float*)d_in[4];
    const float* b_lin  = (const float*)d_in[5];
    float* out = (float*)d_out;

    // Stage W_hh into __constant__ with 32-float row pitch (graph-capturable D2D copy).
    void* cptr = nullptr;
    cudaGetSymbolAddress(&cptr, cP);
    cudaMemcpy2DAsync(cptr, 32 * sizeof(float),
                      W_hh, HID * sizeof(float),
                      HID * sizeof(float), HID,
                      cudaMemcpyDeviceToDevice);

    const int B = in_sizes[0] / SEQLEN;
    const int threads = 128;
    const int blocks = (B + threads - 1) / threads;
    rnn_modrelu_hybrid<<<blocks, threads>>>(inputs, W_ih, W_hh, b_mod, W_lin, b_lin, out, B);
}